// round 2
// baseline (speedup 1.0000x reference)
#include <cuda_runtime.h>

#define TILE_E    128
#define KDIM      256
#define NDIM      64
#define THREADS   256
#define XS_STRIDE 130   // padded row stride (floats): conflict-free scalar stores, 8B-aligned rows

typedef unsigned long long ull;

__device__ int g_idx_is32;   // 1 if edge_index is int32, 0 if int64

__device__ __forceinline__ ull pack_dup(float v) {
    ull r; asm("mov.b64 %0, {%1, %1};" : "=l"(r) : "f"(v)); return r;
}
__device__ __forceinline__ void fma2(ull& d, ull a, ull b) {
    asm("fma.rn.f32x2 %0, %1, %2, %0;" : "+l"(d) : "l"(a), "l"(b));
}
__device__ __forceinline__ void unpack2(ull v, float& lo, float& hi) {
    asm("mov.b64 {%0, %1}, %2;" : "=f"(lo), "=f"(hi) : "l"(v));
}

// Probe: sample odd 32-bit words. int64 ids < 2^31 have zero high words;
// int32 data has random ids there. Deterministic for fixed input.
__global__ void probe_idx_dtype(const int* __restrict__ ei_words, int n_words)
{
    int any = 0;
    for (int i = threadIdx.x * 2 + 1; i < n_words && i < 8192; i += 64)
        any |= ei_words[i];
    any = __any_sync(0xffffffffu, any != 0);
    if (threadIdx.x == 0) g_idx_is32 = any ? 1 : 0;
}

__global__ __launch_bounds__(THREADS, 1)
void edge_mlp_kernel(const float* __restrict__ node_emb,
                     const void* __restrict__ edge_index,
                     const float* __restrict__ W1,
                     const float* __restrict__ b1,
                     const float* __restrict__ W2,
                     const float* __restrict__ b2,
                     float* __restrict__ out,
                     int E, int n_nodes)
{
    extern __shared__ float smem[];
    float* XsT = smem;                    // [KDIM][XS_STRIDE]  gathered X, k-major
    float* Ws  = smem + KDIM * XS_STRIDE; // [KDIM][NDIM]
    __shared__ int sNode[2 * TILE_E];

    const int tid = threadIdx.x;
    const int e0  = blockIdx.x * TILE_E;

    // ---- stage edge indices (256 threads == 2*TILE_E), dtype-dispatched ----
    {
        const int half = tid >> 7;        // 0 = src, 1 = dst
        const int e    = tid & 127;
        const int ge   = e0 + e;
        long long idx  = 0;
        if (ge < E) {
            if (g_idx_is32)
                idx = ((const int*)edge_index)[(long long)half * E + ge];
            else
                idx = ((const long long*)edge_index)[(long long)half * E + ge];
        }
        // defensive clamp: if dtype inference is ever wrong we get rel_err, not a fault
        if (idx < 0) idx = 0;
        if (idx >= n_nodes) idx = n_nodes - 1;
        sNode[half * TILE_E + e] = (int)idx;
    }

    // ---- stage W1 (coalesced float4 copy) ----
    {
        const float4* w4  = (const float4*)W1;
        float4*       ws4 = (float4*)Ws;
        #pragma unroll
        for (int i = 0; i < (KDIM * NDIM / 4) / THREADS; ++i)
            ws4[i * THREADS + tid] = w4[i * THREADS + tid];
    }
    __syncthreads();

    // ---- gather X transposed: XsT[k][e] = feature k of edge e ----
    {
        const int k    = tid;           // 0..255 : k<128 -> src half, k>=128 -> dst half
        const int koff = k & 128;       // selects src/dst slot in sNode
        const int kk   = k & 127;
        float* xcol = XsT + k * XS_STRIDE;
        #pragma unroll 4
        for (int e = 0; e < TILE_E; ++e) {
            int node = sNode[koff + e];
            xcol[e] = node_emb[(long long)node * 128 + kk];  // coalesced along k across threads
        }
    }
    __syncthreads();

    // ---- GEMM: C[128][64], thread tile = 8 edges (4 f32x2 pairs) x 4 cols ----
    const int tx = tid & 15;   // col group: cols tx*4 .. tx*4+3
    const int ey = tid >> 4;   // edge group: edges ey*8 .. ey*8+7

    const float* xbase = XsT + ey * 8;
    const float* wbase = Ws  + tx * 4;

    ull acc[4][4];
    #pragma unroll
    for (int i = 0; i < 4; ++i)
        #pragma unroll
        for (int j = 0; j < 4; ++j) acc[i][j] = 0ULL;

    #pragma unroll 4
    for (int k = 0; k < KDIM; ++k) {
        const ull* xr = (const ull*)(xbase + k * XS_STRIDE); // 4 packed edge-pairs (broadcast LDS.64)
        ull xa[4];
        xa[0] = xr[0]; xa[1] = xr[1]; xa[2] = xr[2]; xa[3] = xr[3];
        float4 w = *(const float4*)(wbase + k * NDIM);
        ull wd[4];
        wd[0] = pack_dup(w.x); wd[1] = pack_dup(w.y);
        wd[2] = pack_dup(w.z); wd[3] = pack_dup(w.w);
        #pragma unroll
        for (int i = 0; i < 4; ++i)
            #pragma unroll
            for (int j = 0; j < 4; ++j)
                fma2(acc[i][j], xa[i], wd[j]);   // 16 FFMA2 = 32 MACs/thread/k
    }

    // ---- epilogue: relu(C + b1) . W2, reduce across the 16 col-threads ----
    float b1v[4], w2v[4];
    #pragma unroll
    for (int j = 0; j < 4; ++j) {
        b1v[j] = b1[tx * 4 + j];
        w2v[j] = W2[tx * 4 + j];
    }
    float p[8];
    #pragma unroll
    for (int i = 0; i < 8; ++i) p[i] = 0.f;

    #pragma unroll
    for (int i2 = 0; i2 < 4; ++i2)
        #pragma unroll
        for (int j = 0; j < 4; ++j) {
            float lo, hi; unpack2(acc[i2][j], lo, hi);
            lo = fmaxf(lo + b1v[j], 0.f);
            hi = fmaxf(hi + b1v[j], 0.f);
            p[2 * i2]     = fmaf(lo, w2v[j], p[2 * i2]);
            p[2 * i2 + 1] = fmaf(hi, w2v[j], p[2 * i2 + 1]);
        }

    // reduce over tx (lanes 0..15 / 16..31 of each warp; xor offsets stay in-half)
    #pragma unroll
    for (int off = 8; off; off >>= 1)
        #pragma unroll
        for (int i = 0; i < 8; ++i)
            p[i] += __shfl_xor_sync(0xffffffffu, p[i], off);

    if (tx == 0) {
        const float bb = b2[0];
        const int ebase = e0 + ey * 8;
        #pragma unroll
        for (int i = 0; i < 8; ++i)
            if (ebase + i < E) out[ebase + i] = p[i] + bb;
    }
}

extern "C" void kernel_launch(void* const* d_in, const int* in_sizes, int n_in,
                              void* d_out, int out_size)
{
    const float* node_emb   = (const float*)d_in[0];
    const void*  edge_index = d_in[1];
    const float* W1         = (const float*)d_in[2];
    const float* b1         = (const float*)d_in[3];
    const float* W2         = (const float*)d_in[4];
    const float* b2         = (const float*)d_in[5];
    float*       out        = (float*)d_out;

    const int E       = out_size;              // one logit per edge (dtype-independent)
    const int n_nodes = in_sizes[0] / 128;     // node_emb is [N, 128] f32

    // words to scan if data were int32 (2*E words) — probe caps itself at 8192
    probe_idx_dtype<<<1, 32>>>((const int*)edge_index, 2 * E);

    const size_t smem_bytes = (size_t)(KDIM * XS_STRIDE + KDIM * NDIM) * sizeof(float); // ~194 KB
    cudaFuncSetAttribute(edge_mlp_kernel,
                         cudaFuncAttributeMaxDynamicSharedMemorySize, (int)smem_bytes);

    const int grid = (E + TILE_E - 1) / TILE_E;  // 6250 for E=800000
    edge_mlp_kernel<<<grid, THREADS, smem_bytes>>>(node_emb, edge_index, W1, b1, W2, b2,
                                                   out, E, n_nodes);
}